// round 11
// baseline (speedup 1.0000x reference)
#include <cuda_runtime.h>
#include <cuda_bf16.h>
#include <cuda_fp16.h>
#include <cstdint>
#include <cstddef>

#define NN 50000
#define NE 800000
#define CONV_BLKS ((NN * 32 + 255) / 256)
#define NB 148
#define CSR_T 256
#define CHUNK 338   // 148*338 = 50024 >= 50000

// ---------------- scratch (static device globals) ----------------
__device__ int   g_cnt[NN];
__device__ int   g_rowptr[NN + 1];
__device__ int   g_wr[NN];
__device__ int   g_csr[NE];
__device__ float g_dinv[NN];
__device__ __nv_bfloat16 g_xhi[(size_t)NN * 128];
__device__ __nv_bfloat16 g_xlo[(size_t)NN * 128];
__device__ __half        g_ylh[(size_t)NN * 128];
__device__ float         g_yrf[(size_t)NN * 128];
__device__ __nv_bfloat16 g_wt[3 * 256 * 256];
__device__ unsigned g_bgen = 0;
__device__ unsigned g_bcnt = 0;
__device__ int g_bsum[NB];
__device__ int g_boff[NB];

// ---------------- PTX helpers (base ISA only) ----------------
__device__ __forceinline__ uint32_t su32(const void* p) {
    uint32_t a;
    asm("{ .reg .u64 t; cvta.to.shared.u64 t, %1; cvt.u32.u64 %0, t; }" : "=r"(a) : "l"(p));
    return a;
}
__device__ __forceinline__ void ldsm4(uint32_t* r, uint32_t addr) {
    asm volatile("ldmatrix.sync.aligned.m8n8.x4.shared.b16 {%0,%1,%2,%3}, [%4];"
                 : "=r"(r[0]), "=r"(r[1]), "=r"(r[2]), "=r"(r[3]) : "r"(addr));
}
__device__ __forceinline__ void mma16816(float* d, const uint32_t* a, const uint32_t* b) {
    asm volatile(
        "mma.sync.aligned.m16n8k16.row.col.f32.bf16.bf16.f32 "
        "{%0,%1,%2,%3}, {%4,%5,%6,%7}, {%8,%9}, {%0,%1,%2,%3};"
        : "+f"(d[0]), "+f"(d[1]), "+f"(d[2]), "+f"(d[3])
        : "r"(a[0]), "r"(a[1]), "r"(a[2]), "r"(a[3]), "r"(b[0]), "r"(b[1]));
}
__device__ __forceinline__ void cpasync16(uint32_t dst, const void* src, uint32_t sz) {
    asm volatile("cp.async.cg.shared.global [%0], [%1], 16, %2;"
                 :: "r"(dst), "l"(src), "r"(sz) : "memory");
}
#define CP_COMMIT() asm volatile("cp.async.commit_group;" ::: "memory")
#define CP_WAIT(n)  asm volatile("cp.async.wait_group %0;" :: "n"(n) : "memory")

// ---------------- software grid barrier (148 co-resident blocks) ----------------
__device__ __forceinline__ void gbar() {
    __threadfence();
    __syncthreads();
    if (threadIdx.x == 0) {
        unsigned gen = *(volatile unsigned*)&g_bgen;
        if (atomicAdd(&g_bcnt, 1u) == NB - 1) {
            g_bcnt = 0;
            __threadfence();
            atomicExch(&g_bgen, gen + 1);
        } else {
            while (*(volatile unsigned*)&g_bgen == gen) {}
        }
    }
    __syncthreads();
    __threadfence();
}

// ---------------- fused CSR build: zero + hist + scan + scatter ----------------
__global__ void __launch_bounds__(CSR_T)
csr_fused(const int* __restrict__ src, const int* __restrict__ dst) {
    int b = blockIdx.x, t = threadIdx.x;
    int gt = b * CSR_T + t;
    const int gstride = NB * CSR_T;
    __shared__ int sc[CSR_T];

    for (int i = gt; i < NN; i += gstride) g_cnt[i] = 0;
    gbar();
    for (int e = gt; e < NE; e += gstride) atomicAdd(&g_cnt[dst[e]], 1);
    gbar();
    int i0 = b * CHUNK;
    int e0 = i0 + t * 2;
    int c0 = 0, c1 = 0;
    if (t * 2 < CHUNK) {
        if (e0 < NN) c0 = g_cnt[e0];
        if (t * 2 + 1 < CHUNK && e0 + 1 < NN) c1 = g_cnt[e0 + 1];
    }
    sc[t] = c0 + c1;
    __syncthreads();
    for (int off = 1; off < CSR_T; off <<= 1) {
        int v = (t >= off) ? sc[t - off] : 0;
        __syncthreads();
        sc[t] += v;
        __syncthreads();
    }
    int excl = t ? sc[t - 1] : 0;
    if (t == CSR_T - 1) g_bsum[b] = sc[t];
    gbar();
    if (b == 0) {
        sc[t] = (t < NB) ? g_bsum[t] : 0;
        __syncthreads();
        for (int off = 1; off < CSR_T; off <<= 1) {
            int v = (t >= off) ? sc[t - off] : 0;
            __syncthreads();
            sc[t] += v;
            __syncthreads();
        }
        if (t < NB) g_boff[t] = t ? sc[t - 1] : 0;
    }
    gbar();
    {
        int base = g_boff[b] + excl;
        if (t * 2 < CHUNK && e0 < NN) {
            g_rowptr[e0] = base;
            g_wr[e0] = base;
            g_dinv[e0] = 1.0f / (float)(c0 > 1 ? c0 : 1);
            if (t * 2 + 1 < CHUNK && e0 + 1 < NN) {
                g_rowptr[e0 + 1] = base + c0;
                g_wr[e0 + 1] = base + c0;
                g_dinv[e0 + 1] = 1.0f / (float)(c1 > 1 ? c1 : 1);
            }
        }
        if (b == 0 && t == 0) g_rowptr[NN] = NE;
    }
    gbar();
    for (int e = gt; e < NE; e += gstride) {
        int p = atomicAdd(&g_wr[dst[e]], 1);
        g_csr[p] = src[e];
    }
}

// ---------------- prep A: input split ----------------
__global__ void prep_conv(const float* __restrict__ x,
                          __nv_bfloat16* __restrict__ xh, __nv_bfloat16* __restrict__ xl)
{
    size_t i = (size_t)blockIdx.x * 256 + threadIdx.x;
    if (i >= (size_t)NN * 32) return;
    float4 v = *(const float4*)(x + i * 4);
    __nv_bfloat16 h0 = __float2bfloat16_rn(v.x), h1 = __float2bfloat16_rn(v.y);
    __nv_bfloat16 h2 = __float2bfloat16_rn(v.z), h3 = __float2bfloat16_rn(v.w);
    __nv_bfloat162 a0 = {h0, h1}, a1 = {h2, h3};
    __nv_bfloat162 b0 = {__float2bfloat16_rn(v.x - __bfloat162float(h0)),
                         __float2bfloat16_rn(v.y - __bfloat162float(h1))};
    __nv_bfloat162 b1 = {__float2bfloat16_rn(v.z - __bfloat162float(h2)),
                         __float2bfloat16_rn(v.w - __bfloat162float(h3))};
    uint2 uh, ul;
    uh.x = *(uint32_t*)&a0; uh.y = *(uint32_t*)&a1;
    ul.x = *(uint32_t*)&b0; ul.y = *(uint32_t*)&b1;
    *(uint2*)(xh + i * 4) = uh;
    *(uint2*)(xl + i * 4) = ul;
}

// ---------------- prep B: weight split/transpose (all 3 layers) ----------------
__global__ void prep_w(const float* __restrict__ wl0, const float* __restrict__ wr0,
                       const float* __restrict__ wl1, const float* __restrict__ wr1,
                       const float* __restrict__ wl2, const float* __restrict__ wr2,
                       __nv_bfloat16* __restrict__ Wt)
{
    int wb = blockIdx.x;   // 0..639
    const float *Wl, *Wr;
    int HO, loff;
    if (wb < 256)      { Wl = wl0; Wr = wr0; HO = 128; loff = 0;      }
    else if (wb < 512) { Wl = wl1; Wr = wr1; HO = 128; loff = 65536;  wb -= 256; }
    else               { Wl = wl2; Wr = wr2; HO = 64;  loff = 131072; wb -= 512; }
    int n = wb, k = threadIdx.x;
    int kk = k & 127;
    const float* W = (n < HO) ? Wl : Wr;
    int nn = (n < HO) ? n : n - HO;
    float v = W[kk * HO + nn];
    __nv_bfloat16 hi = __float2bfloat16_rn(v);
    __nv_bfloat16 o = (k < 128) ? hi : __float2bfloat16_rn(v - __bfloat162float(hi));
    Wt[loff + n * 256 + k] = o;
}

// ---------------- fragment set for one k16 step ----------------
struct KFrag { uint32_t aL[2][4], aH[2][4], bH[2][4], bL[2][4]; };

// ---------------- persistent HMMA GEMM: 512 thr, 4x4 warps, fused + k16-pipelined ----------------
// smem: B_hi 32K@0 | B_lo 32K@32K | Abuf0 (xlo@64K, xhi@96K) | Abuf1 (xlo@128K, xhi@160K) = 192K
__global__ void __launch_bounds__(512)
gemm_pers(const __nv_bfloat16* __restrict__ xhi, const __nv_bfloat16* __restrict__ xlo,
          const __nv_bfloat16* __restrict__ Wt, const float* __restrict__ bias,
          __half* __restrict__ yl, float* __restrict__ yr, int M, int HO)
{
    extern __shared__ char smem[];
    const uint32_t sb = su32(smem);

    int tid = threadIdx.x;
    int wid = tid >> 5, lane = tid & 31;
    int ny = blockIdx.y;
    int hol = HO - ny * 128; hol = hol < 0 ? 0 : (hol > 128 ? 128 : hol);

    int wm = (wid & 3) * 32;
    int wn = (wid >> 2) * 32;

    int row = tid >> 2;
    int ub4 = (tid & 3) * 4;
    uint32_t soff[4];
#pragma unroll
    for (int j = 0; j < 4; j++) soff[j] = (uint32_t)(((ub4 + j) ^ (row & 7)) << 4);

    {
        const __nv_bfloat16* wRow = Wt + (size_t)(ny * 128 + row) * 256;
        uint32_t d0 = sb + row * 256, d1 = sb + 32768 + row * 256;
#pragma unroll
        for (int j = 0; j < 4; j++) {
            cpasync16(d0 + soff[j], wRow + (ub4 + j) * 8, 16u);
            cpasync16(d1 + soff[j], wRow + 128 + (ub4 + j) * 8, 16u);
        }
    }
    int nt = (M + 127) >> 7;
    int step = gridDim.x;

    {
        int m = blockIdx.x * 128 + row;
        uint32_t sz = (m < M) ? 16u : 0u;
        const __nv_bfloat16* aL = xlo + (size_t)m * 128;
        const __nv_bfloat16* aH = xhi + (size_t)m * 128;
        uint32_t dL = sb + 65536 + row * 256, dH = dL + 32768;
#pragma unroll
        for (int j = 0; j < 4; j++) {
            cpasync16(dL + soff[j], aL + (ub4 + j) * 8, sz);
            cpasync16(dH + soff[j], aH + (ub4 + j) * 8, sz);
        }
    }
    CP_COMMIT();

    int rA = wm + (lane & 15);
    uint32_t arow[2]; int xr[2];
#pragma unroll
    for (int mi = 0; mi < 2; mi++) {
        int r = rA + mi * 16;
        arow[mi] = (uint32_t)(r * 256);
        xr[mi] = r & 7;
    }
    int rbB0 = wn + (lane & 7) + ((lane >> 4) << 3);
    uint32_t brow[2]; int xb[2];
#pragma unroll
    for (int nj = 0; nj < 2; nj++) {
        int rb = rbB0 + nj * 16;
        brow[nj] = (uint32_t)(rb * 256);
        xb[nj] = rb & 7;
    }
    int laneA = lane >> 4;
    int laneB = (lane >> 3) & 1;
    int r_lane = lane >> 2;
    int c_lane = (lane & 3) * 2;
    bool isl = (wn < hol);
    int cb_yr = wn - hol;

    int p = 0;
    for (int t = blockIdx.x; t < nt; t += step, p ^= 1) {
        int tn = t + step;
        if (tn < nt) {
            int m = tn * 128 + row;
            uint32_t sz = (m < M) ? 16u : 0u;
            const __nv_bfloat16* aL = xlo + (size_t)m * 128;
            const __nv_bfloat16* aH = xhi + (size_t)m * 128;
            uint32_t dL = sb + 65536 + (p ^ 1) * 65536 + row * 256, dH = dL + 32768;
#pragma unroll
            for (int j = 0; j < 4; j++) {
                cpasync16(dL + soff[j], aL + (ub4 + j) * 8, sz);
                cpasync16(dH + soff[j], aH + (ub4 + j) * 8, sz);
            }
        }
        CP_COMMIT();
        CP_WAIT(1);
        __syncthreads();

        float acc[8][4];
#pragma unroll
        for (int i = 0; i < 8; i++)
#pragma unroll
            for (int j = 0; j < 4; j++) acc[i][j] = 0.f;

        uint32_t abL = sb + 65536 + p * 65536;
        uint32_t abH = abL + 32768;
        uint32_t bH = sb, bL = sb + 32768;

        KFrag f[2];

        // load k16 = 0 fragments
        {
            int ua = laneA, ub = laneB;
#pragma unroll
            for (int mi = 0; mi < 2; mi++) {
                uint32_t so = (uint32_t)((ua ^ xr[mi]) << 4);
                ldsm4(f[0].aL[mi], abL + arow[mi] + so);
                ldsm4(f[0].aH[mi], abH + arow[mi] + so);
            }
#pragma unroll
            for (int nj = 0; nj < 2; nj++) {
                uint32_t so = (uint32_t)((ub ^ xb[nj]) << 4);
                ldsm4(f[0].bH[nj], bH + brow[nj] + so);
                ldsm4(f[0].bL[nj], bL + brow[nj] + so);
            }
        }

#pragma unroll
        for (int k16 = 0; k16 < 8; k16++) {
            KFrag& cur = f[k16 & 1];
            KFrag& nxt = f[(k16 + 1) & 1];
            if (k16 < 7) {
                int ua = ((k16 + 1) << 1) + laneA;
                int ub = ((k16 + 1) << 1) + laneB;
#pragma unroll
                for (int mi = 0; mi < 2; mi++) {
                    uint32_t so = (uint32_t)((ua ^ xr[mi]) << 4);
                    ldsm4(nxt.aL[mi], abL + arow[mi] + so);
                    ldsm4(nxt.aH[mi], abH + arow[mi] + so);
                }
#pragma unroll
                for (int nj = 0; nj < 2; nj++) {
                    uint32_t so = (uint32_t)((ub ^ xb[nj]) << 4);
                    ldsm4(nxt.bH[nj], bH + brow[nj] + so);
                    ldsm4(nxt.bL[nj], bL + brow[nj] + so);
                }
            }
#pragma unroll
            for (int mi = 0; mi < 2; mi++)
#pragma unroll
                for (int nj2 = 0; nj2 < 4; nj2++)
                    mma16816(acc[mi * 4 + nj2], cur.aL[mi], &cur.bH[nj2 >> 1][(nj2 & 1) * 2]);
#pragma unroll
            for (int mi = 0; mi < 2; mi++)
#pragma unroll
                for (int nj2 = 0; nj2 < 4; nj2++)
                    mma16816(acc[mi * 4 + nj2], cur.aH[mi], &cur.bH[nj2 >> 1][(nj2 & 1) * 2]);
#pragma unroll
            for (int mi = 0; mi < 2; mi++)
#pragma unroll
                for (int nj2 = 0; nj2 < 4; nj2++)
                    mma16816(acc[mi * 4 + nj2], cur.aH[mi], &cur.bL[nj2 >> 1][(nj2 & 1) * 2]);
        }

        int m0 = t * 128;
        if (isl) {
#pragma unroll
            for (int mi = 0; mi < 2; mi++) {
                int mb = m0 + wm + mi * 16 + r_lane;
#pragma unroll
                for (int nj2 = 0; nj2 < 4; nj2++) {
                    float* d = acc[mi * 4 + nj2];
                    int col = wn + nj2 * 8 + c_lane;
                    __half2 h01 = __floats2half2_rn(d[0], d[1]);
                    __half2 h23 = __floats2half2_rn(d[2], d[3]);
                    if (mb < M)     *(__half2*)(yl + (size_t)mb * HO + col) = h01;
                    if (mb + 8 < M) *(__half2*)(yl + (size_t)(mb + 8) * HO + col) = h23;
                }
            }
        } else {
#pragma unroll
            for (int mi = 0; mi < 2; mi++) {
                int mb = m0 + wm + mi * 16 + r_lane;
#pragma unroll
                for (int nj2 = 0; nj2 < 4; nj2++) {
                    float* d = acc[mi * 4 + nj2];
                    int col = cb_yr + nj2 * 8 + c_lane;
                    float2 bv = *(const float2*)(bias + col);
                    float2 v01 = make_float2(d[0] + bv.x, d[1] + bv.y);
                    float2 v23 = make_float2(d[2] + bv.x, d[3] + bv.y);
                    if (mb < M)     *(float2*)(yr + (size_t)mb * HO + col) = v01;
                    if (mb + 8 < M) *(float2*)(yr + (size_t)(mb + 8) * HO + col) = v23;
                }
            }
        }
        __syncthreads();
    }
}

// ---------------- aggregation (H=128): relu(mean + yr) -> split bf16 hi/lo, 8-way unrolled ----------------
__global__ void agg128_kernel(const __half* __restrict__ yl, const float* __restrict__ yrv,
                              __nv_bfloat16* __restrict__ xh, __nv_bfloat16* __restrict__ xl, int M)
{
    int gw = (blockIdx.x * blockDim.x + threadIdx.x) >> 5;
    int lane = threadIdx.x & 31;
    if (gw >= M) return;
    int beg = g_rowptr[gw], end = g_rowptr[gw + 1];
    float di = g_dinv[gw];

    float a0 = 0.f, a1 = 0.f, a2 = 0.f, a3 = 0.f;
    const __half* base = yl + lane * 4;
    int e = beg;
    for (; e + 8 <= end; e += 8) {
        int s[8];
#pragma unroll
        for (int j = 0; j < 8; j++) s[j] = g_csr[e + j];
        uint2 r[8];
#pragma unroll
        for (int j = 0; j < 8; j++) r[j] = *(const uint2*)(base + (size_t)s[j] * 128);
#pragma unroll
        for (int j = 0; j < 8; j++) {
            float2 f0 = __half22float2(*(__half2*)&r[j].x), f1 = __half22float2(*(__half2*)&r[j].y);
            a0 += f0.x; a1 += f0.y; a2 += f1.x; a3 += f1.y;
        }
    }
    for (; e + 4 <= end; e += 4) {
        int s[4];
#pragma unroll
        for (int j = 0; j < 4; j++) s[j] = g_csr[e + j];
        uint2 r[4];
#pragma unroll
        for (int j = 0; j < 4; j++) r[j] = *(const uint2*)(base + (size_t)s[j] * 128);
#pragma unroll
        for (int j = 0; j < 4; j++) {
            float2 f0 = __half22float2(*(__half2*)&r[j].x), f1 = __half22float2(*(__half2*)&r[j].y);
            a0 += f0.x; a1 += f0.y; a2 += f1.x; a3 += f1.y;
        }
    }
    for (; e < end; e++) {
        uint2 r0 = *(const uint2*)(base + (size_t)g_csr[e] * 128);
        float2 f0 = __half22float2(*(__half2*)&r0.x), f1 = __half22float2(*(__half2*)&r0.y);
        a0 += f0.x; a1 += f0.y; a2 += f1.x; a3 += f1.y;
    }
    float4 r = *(const float4*)(yrv + (size_t)gw * 128 + lane * 4);
    float v0 = fmaxf(a0 * di + r.x, 0.f);
    float v1 = fmaxf(a1 * di + r.y, 0.f);
    float v2 = fmaxf(a2 * di + r.z, 0.f);
    float v3 = fmaxf(a3 * di + r.w, 0.f);

    __nv_bfloat16 h0 = __float2bfloat16_rn(v0), h1 = __float2bfloat16_rn(v1);
    __nv_bfloat16 h2 = __float2bfloat16_rn(v2), h3 = __float2bfloat16_rn(v3);
    __nv_bfloat162 ph0 = {h0, h1}, ph1 = {h2, h3};
    __nv_bfloat162 pl0 = {__float2bfloat16_rn(v0 - __bfloat162float(h0)),
                          __float2bfloat16_rn(v1 - __bfloat162float(h1))};
    __nv_bfloat162 pl1 = {__float2bfloat16_rn(v2 - __bfloat162float(h2)),
                          __float2bfloat16_rn(v3 - __bfloat162float(h3))};
    uint2 uh, ul;
    uh.x = *(uint32_t*)&ph0; uh.y = *(uint32_t*)&ph1;
    ul.x = *(uint32_t*)&pl0; ul.y = *(uint32_t*)&pl1;
    *(uint2*)(xh + (size_t)gw * 128 + lane * 4) = uh;
    *(uint2*)(xl + (size_t)gw * 128 + lane * 4) = ul;
}

// ---------------- aggregation (H=64) fused with classifier head ----------------
__global__ void agg64_head_kernel(const __half* __restrict__ yl, const float* __restrict__ yrv,
                                  const float* __restrict__ wout, const float* __restrict__ bout,
                                  float* __restrict__ out, int M)
{
    __shared__ float ws[256];
    __shared__ float bs[4];
    int t = threadIdx.x;
    ws[t] = wout[t];
    if (t < 4) bs[t] = bout[t];
    __syncthreads();
    int gw = blockIdx.x * 8 + (t >> 5);
    int lane = t & 31;
    if (gw >= M) return;
    int beg = g_rowptr[gw], end = g_rowptr[gw + 1];
    float di = g_dinv[gw];

    float a0 = 0.f, a1 = 0.f;
    const __half* base = yl + lane * 2;
    int e = beg;
    for (; e + 4 <= end; e += 4) {
        int s0 = g_csr[e], s1 = g_csr[e + 1], s2 = g_csr[e + 2], s3 = g_csr[e + 3];
        float2 f0 = __half22float2(*(const __half2*)(base + (size_t)s0 * 64));
        float2 f1 = __half22float2(*(const __half2*)(base + (size_t)s1 * 64));
        float2 f2 = __half22float2(*(const __half2*)(base + (size_t)s2 * 64));
        float2 f3 = __half22float2(*(const __half2*)(base + (size_t)s3 * 64));
        a0 += (f0.x + f1.x) + (f2.x + f3.x);
        a1 += (f0.y + f1.y) + (f2.y + f3.y);
    }
    for (; e < end; e++) {
        float2 f0 = __half22float2(*(const __half2*)(base + (size_t)g_csr[e] * 64));
        a0 += f0.x; a1 += f0.y;
    }
    float2 r = *(const float2*)(yrv + (size_t)gw * 64 + lane * 2);
    float v0 = fmaxf(a0 * di + r.x, 0.f);
    float v1 = fmaxf(a1 * di + r.y, 0.f);

    float acc[4];
#pragma unroll
    for (int c = 0; c < 4; c++)
        acc[c] = v0 * ws[(lane * 2) * 4 + c] + v1 * ws[(lane * 2 + 1) * 4 + c];
#pragma unroll
    for (int off = 16; off > 0; off >>= 1) {
#pragma unroll
        for (int c = 0; c < 4; c++)
            acc[c] += __shfl_xor_sync(0xFFFFFFFF, acc[c], off);
    }
    if (lane == 0) {
        float4 o = make_float4(acc[0] + bs[0], acc[1] + bs[1], acc[2] + bs[2], acc[3] + bs[3]);
        *(float4*)(out + (size_t)gw * 4) = o;
    }
}

// ---------------- launch ----------------
extern "C" void kernel_launch(void* const* d_in, const int* in_sizes, int n_in,
                              void* d_out, int out_size)
{
    (void)in_sizes; (void)n_in; (void)out_size;
    const float* x     = (const float*)d_in[0];
    const int*   ei    = (const int*)d_in[1];
    const float* w_l0  = (const float*)d_in[3];
    const float* w_r0  = (const float*)d_in[4];
    const float* b0    = (const float*)d_in[5];
    const float* w_l1  = (const float*)d_in[6];
    const float* w_r1  = (const float*)d_in[7];
    const float* b1    = (const float*)d_in[8];
    const float* w_l2  = (const float*)d_in[9];
    const float* w_r2  = (const float*)d_in[10];
    const float* b2    = (const float*)d_in[11];
    const float* w_out = (const float*)d_in[12];
    const float* b_out = (const float*)d_in[13];
    float* out = (float*)d_out;

    const int* srcp = ei;
    const int* dstp = ei + NE;

    __nv_bfloat16 *xhi, *xlo, *wt;
    __half* ylh;
    float* yrf;
    cudaGetSymbolAddress((void**)&xhi, g_xhi);
    cudaGetSymbolAddress((void**)&xlo, g_xlo);
    cudaGetSymbolAddress((void**)&ylh, g_ylh);
    cudaGetSymbolAddress((void**)&yrf, g_yrf);
    cudaGetSymbolAddress((void**)&wt,  g_wt);

    static cudaStream_t s2 = nullptr;
    static cudaEvent_t evFork = nullptr, evJoin = nullptr;
    if (!s2) {
        cudaStreamCreateWithFlags(&s2, cudaStreamNonBlocking);
        cudaEventCreateWithFlags(&evFork, cudaEventDisableTiming);
        cudaEventCreateWithFlags(&evJoin, cudaEventDisableTiming);
        cudaFuncSetAttribute(gemm_pers, cudaFuncAttributeMaxDynamicSharedMemorySize, 196608);
    }

    int ablk = (NN + 7) / 8;

    cudaEventRecord(evFork, 0);
    cudaStreamWaitEvent(s2, evFork, 0);

    // #1 (s2): fused CSR build
    csr_fused<<<NB, CSR_T, 0, s2>>>(srcp, dstp);
    cudaEventRecord(evJoin, s2);
    // #2 (main): input split
    prep_conv<<<CONV_BLKS, 256>>>(x, xhi, xlo);
    // #3 (main): weight prep
    prep_w<<<640, 256>>>(w_l0, w_r0, w_l1, w_r1, w_l2, w_r2, wt);
    // #4 (main): layer-0 GEMM  <-- ncu capture target
    gemm_pers<<<dim3(74, 2), 512, 196608>>>(xhi, xlo, wt, b0, ylh, yrf, NN, 128);
    // join: aggregation needs CSR
    cudaStreamWaitEvent(0, evJoin, 0);
    // #5..#8
    agg128_kernel<<<ablk, 256>>>(ylh, yrf, xhi, xlo, NN);
    gemm_pers<<<dim3(74, 2), 512, 196608>>>(xhi, xlo, wt + 65536, b1, ylh, yrf, NN, 128);
    agg128_kernel<<<ablk, 256>>>(ylh, yrf, xhi, xlo, NN);
    gemm_pers<<<dim3(148, 1), 512, 196608>>>(xhi, xlo, wt + 131072, b2, ylh, yrf, NN, 64);
    agg64_head_kernel<<<ablk, 256>>>(ylh, yrf, w_out, b_out, out, NN);
}

// round 12
// speedup vs baseline: 1.2512x; 1.2512x over previous
#include <cuda_runtime.h>
#include <cuda_fp16.h>
#include <cstdint>
#include <cstddef>

#define NN 50000
#define NE 800000
#define CONV_BLKS ((NN * 32 + 255) / 256)
#define NB 148
#define CSR_T 256
#define CHUNK 338   // 148*338 = 50024 >= 50000

// ---------------- scratch (static device globals) ----------------
__device__ int   g_cnt[NN];
__device__ int   g_rowptr[NN + 1];
__device__ int   g_wr[NN];
__device__ int   g_csr[NE];
__device__ float g_dinv[NN];
__device__ __half g_xh[(size_t)NN * 128];
__device__ __half g_ylh[(size_t)NN * 128];
__device__ float  g_yrf[(size_t)NN * 128];
__device__ __half g_wt[2 * 256 * 128 + 128 * 128];   // L0,L1: 256x128 ; L2: 128x128
__device__ unsigned g_bgen = 0;
__device__ unsigned g_bcnt = 0;
__device__ int g_bsum[NB];
__device__ int g_boff[NB];

// ---------------- PTX helpers (base ISA only) ----------------
__device__ __forceinline__ uint32_t su32(const void* p) {
    uint32_t a;
    asm("{ .reg .u64 t; cvta.to.shared.u64 t, %1; cvt.u32.u64 %0, t; }" : "=r"(a) : "l"(p));
    return a;
}
__device__ __forceinline__ void ldsm4(uint32_t* r, uint32_t addr) {
    asm volatile("ldmatrix.sync.aligned.m8n8.x4.shared.b16 {%0,%1,%2,%3}, [%4];"
                 : "=r"(r[0]), "=r"(r[1]), "=r"(r[2]), "=r"(r[3]) : "r"(addr));
}
__device__ __forceinline__ void mma16816h(float* d, const uint32_t* a, const uint32_t* b) {
    asm volatile(
        "mma.sync.aligned.m16n8k16.row.col.f32.f16.f16.f32 "
        "{%0,%1,%2,%3}, {%4,%5,%6,%7}, {%8,%9}, {%0,%1,%2,%3};"
        : "+f"(d[0]), "+f"(d[1]), "+f"(d[2]), "+f"(d[3])
        : "r"(a[0]), "r"(a[1]), "r"(a[2]), "r"(a[3]), "r"(b[0]), "r"(b[1]));
}
__device__ __forceinline__ void cpasync16(uint32_t dst, const void* src, uint32_t sz) {
    asm volatile("cp.async.cg.shared.global [%0], [%1], 16, %2;"
                 :: "r"(dst), "l"(src), "r"(sz) : "memory");
}
#define CP_COMMIT() asm volatile("cp.async.commit_group;" ::: "memory")
#define CP_WAIT(n)  asm volatile("cp.async.wait_group %0;" :: "n"(n) : "memory")

// ---------------- software grid barrier ----------------
__device__ __forceinline__ void gbar() {
    __threadfence();
    __syncthreads();
    if (threadIdx.x == 0) {
        unsigned gen = *(volatile unsigned*)&g_bgen;
        if (atomicAdd(&g_bcnt, 1u) == NB - 1) {
            g_bcnt = 0;
            __threadfence();
            atomicExch(&g_bgen, gen + 1);
        } else {
            while (*(volatile unsigned*)&g_bgen == gen) {}
        }
    }
    __syncthreads();
    __threadfence();
}

// ---------------- fused CSR build ----------------
__global__ void __launch_bounds__(CSR_T)
csr_fused(const int* __restrict__ src, const int* __restrict__ dst) {
    int b = blockIdx.x, t = threadIdx.x;
    int gt = b * CSR_T + t;
    const int gstride = NB * CSR_T;
    __shared__ int sc[CSR_T];

    for (int i = gt; i < NN; i += gstride) g_cnt[i] = 0;
    gbar();
    for (int e = gt; e < NE; e += gstride) atomicAdd(&g_cnt[dst[e]], 1);
    gbar();
    int i0 = b * CHUNK;
    int e0 = i0 + t * 2;
    int c0 = 0, c1 = 0;
    if (t * 2 < CHUNK) {
        if (e0 < NN) c0 = g_cnt[e0];
        if (t * 2 + 1 < CHUNK && e0 + 1 < NN) c1 = g_cnt[e0 + 1];
    }
    sc[t] = c0 + c1;
    __syncthreads();
    for (int off = 1; off < CSR_T; off <<= 1) {
        int v = (t >= off) ? sc[t - off] : 0;
        __syncthreads();
        sc[t] += v;
        __syncthreads();
    }
    int excl = t ? sc[t - 1] : 0;
    if (t == CSR_T - 1) g_bsum[b] = sc[t];
    gbar();
    if (b == 0) {
        sc[t] = (t < NB) ? g_bsum[t] : 0;
        __syncthreads();
        for (int off = 1; off < CSR_T; off <<= 1) {
            int v = (t >= off) ? sc[t - off] : 0;
            __syncthreads();
            sc[t] += v;
            __syncthreads();
        }
        if (t < NB) g_boff[t] = t ? sc[t - 1] : 0;
    }
    gbar();
    {
        int base = g_boff[b] + excl;
        if (t * 2 < CHUNK && e0 < NN) {
            g_rowptr[e0] = base;
            g_wr[e0] = base;
            g_dinv[e0] = 1.0f / (float)(c0 > 1 ? c0 : 1);
            if (t * 2 + 1 < CHUNK && e0 + 1 < NN) {
                g_rowptr[e0 + 1] = base + c0;
                g_wr[e0 + 1] = base + c0;
                g_dinv[e0 + 1] = 1.0f / (float)(c1 > 1 ? c1 : 1);
            }
        }
        if (b == 0 && t == 0) g_rowptr[NN] = NE;
    }
    gbar();
    for (int e = gt; e < NE; e += gstride) {
        int p = atomicAdd(&g_wr[dst[e]], 1);
        g_csr[p] = src[e];
    }
}

// ---------------- prep A: input fp32 -> fp16 ----------------
__global__ void prep_conv(const float* __restrict__ x, __half* __restrict__ xh)
{
    size_t i = (size_t)blockIdx.x * 256 + threadIdx.x;
    if (i >= (size_t)NN * 32) return;
    float4 v = *(const float4*)(x + i * 4);
    __half2 h0 = __floats2half2_rn(v.x, v.y);
    __half2 h1 = __floats2half2_rn(v.z, v.w);
    uint2 u; u.x = *(uint32_t*)&h0; u.y = *(uint32_t*)&h1;
    *(uint2*)(xh + i * 4) = u;
}

// ---------------- prep B: weight fp32 -> fp16, [n over Wl|Wr][k] ----------------
__global__ void prep_w(const float* __restrict__ wl0, const float* __restrict__ wr0,
                       const float* __restrict__ wl1, const float* __restrict__ wr1,
                       const float* __restrict__ wl2, const float* __restrict__ wr2,
                       __half* __restrict__ Wt)
{
    int wb = blockIdx.x;   // 0..639
    const float *Wl, *Wr;
    int HO, loff;
    if (wb < 256)      { Wl = wl0; Wr = wr0; HO = 128; loff = 0;     }
    else if (wb < 512) { Wl = wl1; Wr = wr1; HO = 128; loff = 32768; wb -= 256; }
    else               { Wl = wl2; Wr = wr2; HO = 64;  loff = 65536; wb -= 512; }
    int n = wb, k = threadIdx.x;   // k in [0,128)
    const float* W = (n < HO) ? Wl : Wr;
    int nn = (n < HO) ? n : n - HO;
    Wt[loff + n * 128 + k] = __float2half_rn(W[k * HO + nn]);
}

// ---------------- persistent fp16 HMMA GEMM: 512 thr, 4x4 warps, 32x32 warp tiles ----------------
// smem: B(W) 32K@0 | Abuf0 32K@32K | Abuf1 32K@64K = 96K  -> 2 CTAs/SM
__global__ void __launch_bounds__(512, 2)
gemm_pers(const __half* __restrict__ xh,
          const __half* __restrict__ Wt, const float* __restrict__ bias,
          __half* __restrict__ yl, float* __restrict__ yr, int M, int HO)
{
    extern __shared__ char smem[];
    const uint32_t sb = su32(smem);

    int tid = threadIdx.x;
    int wid = tid >> 5, lane = tid & 31;
    int ny = blockIdx.y;
    int hol = HO - ny * 128; hol = hol < 0 ? 0 : (hol > 128 ? 128 : hol);

    int wm = (wid & 3) * 32;
    int wn = (wid >> 2) * 32;

    // loaders: 512 threads, 4 threads/row, 4 uint4 units each (row = 256B)
    int row = tid >> 2;
    int ub4 = (tid & 3) * 4;
    uint32_t soff[4];
#pragma unroll
    for (int j = 0; j < 4; j++) soff[j] = (uint32_t)(((ub4 + j) ^ (row & 7)) << 4);

    // resident weights (single fp16 image, 32K)
    {
        const __half* wRow = Wt + (size_t)(ny * 128 + row) * 128;
        uint32_t d0 = sb + row * 256;
#pragma unroll
        for (int j = 0; j < 4; j++)
            cpasync16(d0 + soff[j], wRow + (ub4 + j) * 8, 16u);
    }
    int nt = (M + 127) >> 7;
    int step = gridDim.x;

    // prefetch first tile into buf0
    {
        int m = blockIdx.x * 128 + row;
        uint32_t sz = (m < M) ? 16u : 0u;
        const __half* aS = xh + (size_t)m * 128;
        uint32_t dA = sb + 32768 + row * 256;
#pragma unroll
        for (int j = 0; j < 4; j++)
            cpasync16(dA + soff[j], aS + (ub4 + j) * 8, sz);
    }
    CP_COMMIT();

    int rA = wm + (lane & 15);
    uint32_t arow[2]; int xr[2];
#pragma unroll
    for (int mi = 0; mi < 2; mi++) {
        int r = rA + mi * 16;
        arow[mi] = (uint32_t)(r * 256);
        xr[mi] = r & 7;
    }
    int rbB0 = wn + (lane & 7) + ((lane >> 4) << 3);
    uint32_t brow[2]; int xb[2];
#pragma unroll
    for (int nj = 0; nj < 2; nj++) {
        int rb = rbB0 + nj * 16;
        brow[nj] = (uint32_t)(rb * 256);
        xb[nj] = rb & 7;
    }
    int laneA = lane >> 4;
    int laneB = (lane >> 3) & 1;
    int r_lane = lane >> 2;
    int c_lane = (lane & 3) * 2;
    bool isl = (wn < hol);
    int cb_yr = wn - hol;

    int p = 0;
    for (int t = blockIdx.x; t < nt; t += step, p ^= 1) {
        int tn = t + step;
        if (tn < nt) {
            int m = tn * 128 + row;
            uint32_t sz = (m < M) ? 16u : 0u;
            const __half* aS = xh + (size_t)m * 128;
            uint32_t dA = sb + 32768 + (p ^ 1) * 32768 + row * 256;
#pragma unroll
            for (int j = 0; j < 4; j++)
                cpasync16(dA + soff[j], aS + (ub4 + j) * 8, sz);
        }
        CP_COMMIT();
        CP_WAIT(1);
        __syncthreads();

        float acc[8][4];
#pragma unroll
        for (int i = 0; i < 8; i++)
#pragma unroll
            for (int j = 0; j < 4; j++) acc[i][j] = 0.f;

        uint32_t ab = sb + 32768 + p * 32768;
        uint32_t bB = sb;

#pragma unroll
        for (int k16 = 0; k16 < 8; k16++) {
            int ua = (k16 << 1) + laneA;
            int ub = (k16 << 1) + laneB;
            uint32_t af[2][4], bf[2][4];
#pragma unroll
            for (int mi = 0; mi < 2; mi++)
                ldsm4(af[mi], ab + arow[mi] + (uint32_t)((ua ^ xr[mi]) << 4));
#pragma unroll
            for (int nj = 0; nj < 2; nj++)
                ldsm4(bf[nj], bB + brow[nj] + (uint32_t)((ub ^ xb[nj]) << 4));
#pragma unroll
            for (int mi = 0; mi < 2; mi++)
#pragma unroll
                for (int nj2 = 0; nj2 < 4; nj2++)
                    mma16816h(acc[mi * 4 + nj2], af[mi], &bf[nj2 >> 1][(nj2 & 1) * 2]);
        }

        // epilogue: direct STG (quad-coalesced)
        int m0 = t * 128;
        if (isl) {
#pragma unroll
            for (int mi = 0; mi < 2; mi++) {
                int mb = m0 + wm + mi * 16 + r_lane;
#pragma unroll
                for (int nj2 = 0; nj2 < 4; nj2++) {
                    float* d = acc[mi * 4 + nj2];
                    int col = wn + nj2 * 8 + c_lane;
                    __half2 h01 = __floats2half2_rn(d[0], d[1]);
                    __half2 h23 = __floats2half2_rn(d[2], d[3]);
                    if (mb < M)     *(__half2*)(yl + (size_t)mb * HO + col) = h01;
                    if (mb + 8 < M) *(__half2*)(yl + (size_t)(mb + 8) * HO + col) = h23;
                }
            }
        } else {
#pragma unroll
            for (int mi = 0; mi < 2; mi++) {
                int mb = m0 + wm + mi * 16 + r_lane;
#pragma unroll
                for (int nj2 = 0; nj2 < 4; nj2++) {
                    float* d = acc[mi * 4 + nj2];
                    int col = cb_yr + nj2 * 8 + c_lane;
                    float2 bv = *(const float2*)(bias + col);
                    float2 v01 = make_float2(d[0] + bv.x, d[1] + bv.y);
                    float2 v23 = make_float2(d[2] + bv.x, d[3] + bv.y);
                    if (mb < M)     *(float2*)(yr + (size_t)mb * HO + col) = v01;
                    if (mb + 8 < M) *(float2*)(yr + (size_t)(mb + 8) * HO + col) = v23;
                }
            }
        }
        __syncthreads();
    }
}

// ---------------- aggregation (H=128): relu(mean + yr) -> fp16, 8-way unrolled ----------------
__global__ void agg128_kernel(const __half* __restrict__ yl, const float* __restrict__ yrv,
                              __half* __restrict__ xh, int M)
{
    int gw = (blockIdx.x * blockDim.x + threadIdx.x) >> 5;
    int lane = threadIdx.x & 31;
    if (gw >= M) return;
    int beg = g_rowptr[gw], end = g_rowptr[gw + 1];
    float di = g_dinv[gw];

    float a0 = 0.f, a1 = 0.f, a2 = 0.f, a3 = 0.f;
    const __half* base = yl + lane * 4;
    int e = beg;
    for (; e + 8 <= end; e += 8) {
        int s[8];
#pragma unroll
        for (int j = 0; j < 8; j++) s[j] = g_csr[e + j];
        uint2 r[8];
#pragma unroll
        for (int j = 0; j < 8; j++) r[j] = *(const uint2*)(base + (size_t)s[j] * 128);
#pragma unroll
        for (int j = 0; j < 8; j++) {
            float2 f0 = __half22float2(*(__half2*)&r[j].x), f1 = __half22float2(*(__half2*)&r[j].y);
            a0 += f0.x; a1 += f0.y; a2 += f1.x; a3 += f1.y;
        }
    }
    for (; e + 4 <= end; e += 4) {
        int s[4];
#pragma unroll
        for (int j = 0; j < 4; j++) s[j] = g_csr[e + j];
        uint2 r[4];
#pragma unroll
        for (int j = 0; j < 4; j++) r[j] = *(const uint2*)(base + (size_t)s[j] * 128);
#pragma unroll
        for (int j = 0; j < 4; j++) {
            float2 f0 = __half22float2(*(__half2*)&r[j].x), f1 = __half22float2(*(__half2*)&r[j].y);
            a0 += f0.x; a1 += f0.y; a2 += f1.x; a3 += f1.y;
        }
    }
    for (; e < end; e++) {
        uint2 r0 = *(const uint2*)(base + (size_t)g_csr[e] * 128);
        float2 f0 = __half22float2(*(__half2*)&r0.x), f1 = __half22float2(*(__half2*)&r0.y);
        a0 += f0.x; a1 += f0.y; a2 += f1.x; a3 += f1.y;
    }
    float4 r = *(const float4*)(yrv + (size_t)gw * 128 + lane * 4);
    float v0 = fmaxf(a0 * di + r.x, 0.f);
    float v1 = fmaxf(a1 * di + r.y, 0.f);
    float v2 = fmaxf(a2 * di + r.z, 0.f);
    float v3 = fmaxf(a3 * di + r.w, 0.f);

    __half2 h0 = __floats2half2_rn(v0, v1);
    __half2 h1 = __floats2half2_rn(v2, v3);
    uint2 u; u.x = *(uint32_t*)&h0; u.y = *(uint32_t*)&h1;
    *(uint2*)(xh + (size_t)gw * 128 + lane * 4) = u;
}

// ---------------- aggregation (H=64) fused with classifier head ----------------
__global__ void agg64_head_kernel(const __half* __restrict__ yl, const float* __restrict__ yrv,
                                  const float* __restrict__ wout, const float* __restrict__ bout,
                                  float* __restrict__ out, int M)
{
    __shared__ float ws[256];
    __shared__ float bs[4];
    int t = threadIdx.x;
    ws[t] = wout[t];
    if (t < 4) bs[t] = bout[t];
    __syncthreads();
    int gw = blockIdx.x * 8 + (t >> 5);
    int lane = t & 31;
    if (gw >= M) return;
    int beg = g_rowptr[gw], end = g_rowptr[gw + 1];
    float di = g_dinv[gw];

    float a0 = 0.f, a1 = 0.f;
    const __half* base = yl + lane * 2;
    int e = beg;
    for (; e + 4 <= end; e += 4) {
        int s0 = g_csr[e], s1 = g_csr[e + 1], s2 = g_csr[e + 2], s3 = g_csr[e + 3];
        float2 f0 = __half22float2(*(const __half2*)(base + (size_t)s0 * 64));
        float2 f1 = __half22float2(*(const __half2*)(base + (size_t)s1 * 64));
        float2 f2 = __half22float2(*(const __half2*)(base + (size_t)s2 * 64));
        float2 f3 = __half22float2(*(const __half2*)(base + (size_t)s3 * 64));
        a0 += (f0.x + f1.x) + (f2.x + f3.x);
        a1 += (f0.y + f1.y) + (f2.y + f3.y);
    }
    for (; e < end; e++) {
        float2 f0 = __half22float2(*(const __half2*)(base + (size_t)g_csr[e] * 64));
        a0 += f0.x; a1 += f0.y;
    }
    float2 r = *(const float2*)(yrv + (size_t)gw * 64 + lane * 2);
    float v0 = fmaxf(a0 * di + r.x, 0.f);
    float v1 = fmaxf(a1 * di + r.y, 0.f);

    float acc[4];
#pragma unroll
    for (int c = 0; c < 4; c++)
        acc[c] = v0 * ws[(lane * 2) * 4 + c] + v1 * ws[(lane * 2 + 1) * 4 + c];
#pragma unroll
    for (int off = 16; off > 0; off >>= 1) {
#pragma unroll
        for (int c = 0; c < 4; c++)
            acc[c] += __shfl_xor_sync(0xFFFFFFFF, acc[c], off);
    }
    if (lane == 0) {
        float4 o = make_float4(acc[0] + bs[0], acc[1] + bs[1], acc[2] + bs[2], acc[3] + bs[3]);
        *(float4*)(out + (size_t)gw * 4) = o;
    }
}

// ---------------- launch ----------------
extern "C" void kernel_launch(void* const* d_in, const int* in_sizes, int n_in,
                              void* d_out, int out_size)
{
    (void)in_sizes; (void)n_in; (void)out_size;
    const float* x     = (const float*)d_in[0];
    const int*   ei    = (const int*)d_in[1];
    const float* w_l0  = (const float*)d_in[3];
    const float* w_r0  = (const float*)d_in[4];
    const float* b0    = (const float*)d_in[5];
    const float* w_l1  = (const float*)d_in[6];
    const float* w_r1  = (const float*)d_in[7];
    const float* b1    = (const float*)d_in[8];
    const float* w_l2  = (const float*)d_in[9];
    const float* w_r2  = (const float*)d_in[10];
    const float* b2    = (const float*)d_in[11];
    const float* w_out = (const float*)d_in[12];
    const float* b_out = (const float*)d_in[13];
    float* out = (float*)d_out;

    const int* srcp = ei;
    const int* dstp = ei + NE;

    __half *xh, *ylh, *wt;
    float* yrf;
    cudaGetSymbolAddress((void**)&xh,  g_xh);
    cudaGetSymbolAddress((void**)&ylh, g_ylh);
    cudaGetSymbolAddress((void**)&yrf, g_yrf);
    cudaGetSymbolAddress((void**)&wt,  g_wt);

    static cudaStream_t s2 = nullptr;
    static cudaEvent_t evFork = nullptr, evJoin = nullptr;
    if (!s2) {
        cudaStreamCreateWithFlags(&s2, cudaStreamNonBlocking);
        cudaEventCreateWithFlags(&evFork, cudaEventDisableTiming);
        cudaEventCreateWithFlags(&evJoin, cudaEventDisableTiming);
        cudaFuncSetAttribute(gemm_pers, cudaFuncAttributeMaxDynamicSharedMemorySize, 98304);
    }

    int ablk = (NN + 7) / 8;

    cudaEventRecord(evFork, 0);
    cudaStreamWaitEvent(s2, evFork, 0);

    // #1 (s2): fused CSR build
    csr_fused<<<NB, CSR_T, 0, s2>>>(srcp, dstp);
    cudaEventRecord(evJoin, s2);
    // #2 (main): input fp32 -> fp16
    prep_conv<<<CONV_BLKS, 256>>>(x, xh);
    // #3 (main): weight fp32 -> fp16
    prep_w<<<640, 128>>>(w_l0, w_r0, w_l1, w_r1, w_l2, w_r2, wt);
    // #4 (main): layer-0 GEMM  <-- ncu capture target
    gemm_pers<<<dim3(148, 2), 512, 98304>>>(xh, wt, b0, ylh, yrf, NN, 128);
    // join: aggregation needs CSR
    cudaStreamWaitEvent(0, evJoin, 0);
    // #5..#8
    agg128_kernel<<<ablk, 256>>>(ylh, yrf, xh, NN);
    gemm_pers<<<dim3(148, 2), 512, 98304>>>(xh, wt + 32768, b1, ylh, yrf, NN, 128);
    agg128_kernel<<<ablk, 256>>>(ylh, yrf, xh, NN);
    gemm_pers<<<dim3(296, 1), 512, 98304>>>(xh, wt + 65536, b2, ylh, yrf, NN, 64);
    agg64_head_kernel<<<ablk, 256>>>(ylh, yrf, w_out, b_out, out, NN);
}